// round 17
// baseline (speedup 1.0000x reference)
#include <cuda_runtime.h>
#include <cstdint>

// Problem constants (N=2, C=32, H=64, W=128, D=48 fixed by dataset shape)
#define N_   2
#define C_   32
#define H_   64
#define W_   128
#define D_   48
#define WC_  (W_ + D_)           // 176
#define VPR  (WC_ / 4)           // 44 float4 per output row
#define DSTRIDE (H_ * VPR)       // float4 stride between consecutive d slices: 2816
#define DCHUNK 8                 // d-slices per thread (6 chunks total) — swept optimum
#define TPB   352                // = 8 * VPR: block covers exactly 8 output rows/slice

// out[n][c2][d][h][j]  (j in [0,176)), i = 47-d:
//   c2 <  32: out = x[n,c2,h,j]      if i <= j < 128   else 0
//   c2 >= 32: out = y[n,c2-32,h,j-i] if 0 <= j-i < 128 else 0
__global__ void __launch_bounds__(TPB)
cost_volume_kernel(const float* __restrict__ x,
                   const float* __restrict__ y,
                   float4* __restrict__ out)
{
    const int tid = blockIdx.x * blockDim.x + threadIdx.x;
    const int d0  = blockIdx.y * DCHUNK;   // 0, 8, 16, 24, 32, 40

    // tid = rowbase * 44 + j4,  rowbase = (n*64 + c2)*64 + h
    const int j4      = tid % VPR;
    const int rowbase = tid / VPR;

    const int h   = rowbase & 63;
    const int c2h = rowbase >> 6;
    const int c2  = c2h & 63;
    const int n   = c2h >> 6;

    const int j0 = j4 * 4;

    // out float4 index at d=d0
    float4* o = out + ((size_t)(n * 64 + c2) * (D_ * H_) + (size_t)d0 * H_ + h) * VPR + j4;

    if (c2 < C_) {
        // ---------------- x branch ----------------
        const int t0 = (D_ - 1) - j0;   // lane0 valid when d >= t0

        if (j0 >= W_ || d0 + (DCHUNK - 1) < t0 - 3) {
            const float4 z = make_float4(0.f, 0.f, 0.f, 0.f);
            #pragma unroll
            for (int dd = 0; dd < DCHUNK; ++dd) { __stcs(o, z); o += DSTRIDE; }
            return;
        }

        const float4 v =
            *reinterpret_cast<const float4*>(x + (((size_t)n * C_ + c2) * H_ + h) * W_ + j0);

        if (d0 >= t0) {
            #pragma unroll
            for (int dd = 0; dd < DCHUNK; ++dd) { __stcs(o, v); o += DSTRIDE; }
        } else {
            #pragma unroll
            for (int dd = 0; dd < DCHUNK; ++dd) {
                const int d = d0 + dd;
                float4 w;
                w.x = (d >= t0    ) ? v.x : 0.f;
                w.y = (d >= t0 - 1) ? v.y : 0.f;
                w.z = (d >= t0 - 2) ? v.z : 0.f;
                w.w = (d >= t0 - 3) ? v.w : 0.f;
                __stcs(o, w);
                o += DSTRIDE;
            }
        }
    } else {
        // ---------------- y branch: preloaded 12-float window ----------------
        // slice d0+dd, lane k reads y[s0 + dd + k], s0 = j0 + d0 - 47.
        // Union over dd∈[0,8), k∈[0,4) is [s0, s0+10] (11 floats).
        // s0 ≡ 1 (mod 4) since j0,d0 ≡ 0 (mod 4) and -47 ≡ 1 → base = s0-1 is
        // 16B-aligned: 3 aligned float4 loads cover w[0..11].
        const float* row = y + (((size_t)n * C_ + (c2 - C_)) * H_ + h) * W_;
        const int s0   = j0 + d0 - (D_ - 1);
        const int base = s0 - 1;                 // multiple of 4

        float w[12];
        #pragma unroll
        for (int m = 0; m < 3; ++m) {
            const int q = base + 4 * m;
            if (q >= 0 && q + 3 < W_) {
                const float4 t = *reinterpret_cast<const float4*>(row + q);
                w[4*m + 0] = t.x; w[4*m + 1] = t.y;
                w[4*m + 2] = t.z; w[4*m + 3] = t.w;
            } else {
                #pragma unroll
                for (int k = 0; k < 4; ++k) {
                    const int g = q + k;
                    w[4*m + k] = ((unsigned)g < (unsigned)W_) ? __ldg(row + g) : 0.f;
                }
            }
        }

        // w index for (dd, k): (s0 + dd + k) - base = dd + k + 1
        #pragma unroll
        for (int dd = 0; dd < DCHUNK; ++dd) {
            __stcs(o, make_float4(w[dd + 1], w[dd + 2], w[dd + 3], w[dd + 4]));
            o += DSTRIDE;
        }
    }
}

extern "C" void kernel_launch(void* const* d_in, const int* in_sizes, int n_in,
                              void* d_out, int out_size)
{
    const float* x = (const float*)d_in[0];
    const float* y = (const float*)d_in[1];

    // grid.x covers (n, c2, h, j4) = 2*64*64*44 = 360448 threads; 360448/352 = 1024
    const int total_threads = N_ * 2 * C_ * H_ * VPR;
    dim3 grid(total_threads / TPB, D_ / DCHUNK, 1);

    cost_volume_kernel<<<grid, TPB>>>(x, y, (float4*)d_out);
}